// round 1
// baseline (speedup 1.0000x reference)
#include <cuda_runtime.h>
#include <math.h>

// Problem constants
#define Bn  4
#define Hn  128
#define Wn  128
#define HWn (Hn*Wn)

// Intermediate scratch (device globals: no allocation allowed)
__device__ float g_off1[Bn*18*HWn];
__device__ float g_mask1[Bn*9*HWn];
__device__ float g_h   [Bn*64*HWn];
__device__ float g_off2[Bn*18*HWn];
__device__ float g_mask2[Bn*9*HWn];

// ---------------------------------------------------------------------------
// offset/mask conv: y[0:18] = conv3x3(in, w_off)+b_off ; y[18:27] = sigmoid(conv+b_mask)
// Block = 16x16 pixel tile, 256 threads, channel-chunked (CC).
// Weights staged in smem m-fastest (padded to 28) so inner loop is LDS.128 broadcast.
// ---------------------------------------------------------------------------
template<int CIN, int CC>
__global__ __launch_bounds__(256)
void offmask_kernel(const float* __restrict__ in,
                    const float* __restrict__ w_off, const float* __restrict__ b_off,
                    const float* __restrict__ w_mask, const float* __restrict__ b_mask,
                    float* __restrict__ off_out, float* __restrict__ mask_out)
{
    constexpr int NCH = CIN/CC;
    __shared__ float tile[CC][18][18];
    __shared__ float wsh[CC*9][28];   // [c*9+k][m], m padded 27->28

    int tid = threadIdx.x;
    int blk = blockIdx.x;
    int bx = blk & 7;          // Wn/16 == 8
    int by = (blk >> 3) & 7;   // Hn/16 == 8
    int b  = blk >> 6;
    int h0 = by*16, w0 = bx*16;
    int ty = tid >> 4, tx = tid & 15;

    float acc[28];
    #pragma unroll
    for (int i=0;i<28;i++) acc[i] = 0.f;

    for (int ch=0; ch<NCH; ch++){
        int c0 = ch*CC;
        // input tile (with zero halo)
        for (int i=tid; i<CC*18*18; i+=256){
            int c = i/(18*18); int r = (i/18)%18; int col = i%18;
            int gy = h0-1+r, gx = w0-1+col;
            float v = 0.f;
            if (gy>=0 && gy<Hn && gx>=0 && gx<Wn)
                v = in[((b*CIN + c0+c)*Hn + gy)*Wn + gx];
            tile[c][r][col] = v;
        }
        // weights, m-fastest layout; pad column 27 with zero
        for (int i=tid; i<CC*9; i+=256) wsh[i][27] = 0.f;
        for (int i=tid; i<CC*9*27; i+=256){
            int ck = i % (CC*9); int m = i / (CC*9);
            int c = ck/9, k = ck - c*9;
            wsh[ck][m] = (m < 18) ? w_off [(m*CIN + c0+c)*9 + k]
                                  : w_mask[((m-18)*CIN + c0+c)*9 + k];
        }
        __syncthreads();
        #pragma unroll
        for (int c=0;c<CC;c++){
            float nb[9];
            #pragma unroll
            for (int ky=0;ky<3;ky++)
                #pragma unroll
                for (int kx=0;kx<3;kx++)
                    nb[ky*3+kx] = tile[c][ty+ky][tx+kx];
            #pragma unroll
            for (int k=0;k<9;k++){
                float v = nb[k];
                const float4* w4 = (const float4*)(&wsh[c*9+k][0]);
                #pragma unroll
                for (int mg=0; mg<7; mg++){
                    float4 wv = w4[mg];
                    acc[mg*4+0] = fmaf(v, wv.x, acc[mg*4+0]);
                    acc[mg*4+1] = fmaf(v, wv.y, acc[mg*4+1]);
                    acc[mg*4+2] = fmaf(v, wv.z, acc[mg*4+2]);
                    acc[mg*4+3] = fmaf(v, wv.w, acc[mg*4+3]);
                }
            }
        }
        __syncthreads();
    }
    int hw = (h0+ty)*Wn + (w0+tx);
    #pragma unroll
    for (int m=0;m<18;m++)
        off_out[(b*18+m)*HWn + hw] = acc[m] + b_off[m];
    #pragma unroll
    for (int m=0;m<9;m++){
        float v = acc[18+m] + b_mask[m];
        mask_out[(b*9+m)*HWn + hw] = 1.f/(1.f + expf(-v));
    }
}

// ---------------------------------------------------------------------------
// Deformable conv: bilinear-sample CIN channels at 9 offset taps (modulated by
// mask), then implicit GEMM into COUT channels + bias + ReLU.
// Block = 64 contiguous pixels (same b, same row), 256 threads.
// Thread tile: PXT=8 pixels x OCT outputs. Channel chunking CC.
// ---------------------------------------------------------------------------
template<int CIN, int COUT, int CC, int OCT>
__global__ __launch_bounds__(256)
void deform_kernel(const float* __restrict__ in,
                   const float* __restrict__ off, const float* __restrict__ mask,
                   const float* __restrict__ wgt, const float* __restrict__ bias,
                   float* __restrict__ out)
{
    constexpr int TP  = 64;
    constexpr int OG  = COUT/OCT;          // 32 output groups
    constexpr int NPG = 256/OG;            // 8 pixel groups
    constexpr int PXT = TP/NPG;            // 8 pixels per thread
    constexpr int NCH = CIN/CC;
    constexpr int PARAMF = 5*9*TP;         // y0,x0,wy1,wx1,m per (k,p)
    constexpr int WF = CC*9*COUT;          // weight chunk [c][k][o]
    constexpr int SF = 9*CC*TP;            // samp [k][c][p]
    constexpr int MAINF = PARAMF + WF + SF;
    constexpr int OUTF  = COUT*TP;         // epilogue staging (aliases MAINF)
    constexpr int SMEMF = (MAINF > OUTF) ? MAINF : OUTF;
    __shared__ __align__(16) float buf[SMEMF];

    int*   y0_sh  = (int*)buf;             // [9][TP]
    int*   x0_sh  = (int*)(buf + 9*TP);
    float* wy1_sh = buf + 2*9*TP;
    float* wx1_sh = buf + 3*9*TP;
    float* mm_sh  = buf + 4*9*TP;
    float* w_sh   = buf + PARAMF;
    float* samp_sh= buf + PARAMF + WF;

    int tid  = threadIdx.x;
    int base = blockIdx.x * TP;
    int b    = base / HWn;
    int rem  = base - b*HWn;
    int h    = rem / Wn;
    int w0   = rem - h*Wn;

    // Phase 0: bilinear params per (k, pixel)
    for (int s=tid; s<9*TP; s+=256){
        int p = s & (TP-1); int k = s/TP;
        int wpix = w0 + p;
        int hw = h*Wn + wpix;
        float dy = off[(b*18 + 2*k  )*HWn + hw];
        float dx = off[(b*18 + 2*k+1)*HWn + hw];
        float mm = mask[(b*9 + k)*HWn + hw];
        int ky = k/3, kx = k - ky*3;
        float py = dy + (float)(h - 1 + ky);
        float px = dx + (float)(wpix - 1 + kx);
        float fy = floorf(py), fx = floorf(px);
        y0_sh[s]  = (int)fy;
        x0_sh[s]  = (int)fx;
        wy1_sh[s] = py - fy;
        wx1_sh[s] = px - fx;
        mm_sh[s]  = mm;
    }

    float acc[PXT][OCT];
    #pragma unroll
    for (int i=0;i<PXT;i++)
        #pragma unroll
        for (int j=0;j<OCT;j++) acc[i][j] = 0.f;

    int og = tid % OG;      // lanes vary in og -> vectorized distinct weight loads
    int pg = tid / OG;      // whole warp shares pg -> samp loads broadcast

    __syncthreads();

    for (int ch=0; ch<NCH; ch++){
        int c0 = ch*CC;
        // weight chunk: w_sh[c][k][o] = wgt[o][c0+c][k] (coalesced global reads)
        for (int i=tid; i<WF; i+=256){
            int o = i/(CC*9); int r = i - o*(CC*9); int c = r/9, k = r - c*9;
            w_sh[(c*9+k)*COUT + o] = wgt[(o*CIN + c0+c)*9 + k];
        }
        // gather + modulate: samp[k][c][p]
        for (int s=tid; s<9*CC*TP; s+=256){
            int p = s & (TP-1); int cc = (s/TP)%CC; int k = s/(TP*CC);
            int kp = k*TP + p;
            int y0 = y0_sh[kp], x0 = x0_sh[kp];
            float wy1 = wy1_sh[kp], wx1 = wx1_sh[kp];
            float wy0 = 1.f-wy1, wx0 = 1.f-wx1;
            const float* cp = in + (size_t)(b*CIN + c0+cc)*HWn;
            int y1 = y0+1, x1 = x0+1;
            bool vy0 = (unsigned)y0 < (unsigned)Hn;
            bool vy1 = (unsigned)y1 < (unsigned)Hn;
            bool vx0 = (unsigned)x0 < (unsigned)Wn;
            bool vx1 = (unsigned)x1 < (unsigned)Wn;
            float v = 0.f;
            if (vy0 && vx0) v = fmaf(cp[y0*Wn+x0], wy0*wx0, v);
            if (vy0 && vx1) v = fmaf(cp[y0*Wn+x1], wy0*wx1, v);
            if (vy1 && vx0) v = fmaf(cp[y1*Wn+x0], wy1*wx0, v);
            if (vy1 && vx1) v = fmaf(cp[y1*Wn+x1], wy1*wx1, v);
            samp_sh[(k*CC+cc)*TP + p] = v * mm_sh[kp];
        }
        __syncthreads();
        // micro-GEMM: acc[px][oc] += samp[k][c][p] * w[c][k][o]
        #pragma unroll
        for (int c=0;c<CC;c++){
            #pragma unroll
            for (int k=0;k<9;k++){
                float wv[OCT];
                const float* wp = w_sh + (c*9+k)*COUT + og*OCT;
                if constexpr (OCT == 4){
                    float4 t = *(const float4*)wp;
                    wv[0]=t.x; wv[1]=t.y; wv[2]=t.z; wv[3]=t.w;
                } else {
                    float2 t = *(const float2*)wp;
                    wv[0]=t.x; wv[1]=t.y;
                }
                const float* sp = samp_sh + (k*CC+c)*TP + pg*PXT;
                float4 s0 = *(const float4*)sp;
                float4 s1 = *(const float4*)(sp+4);
                float sv[8] = {s0.x,s0.y,s0.z,s0.w,s1.x,s1.y,s1.z,s1.w};
                #pragma unroll
                for (int px=0; px<PXT; px++)
                    #pragma unroll
                    for (int oc=0; oc<OCT; oc++)
                        acc[px][oc] = fmaf(sv[px], wv[oc], acc[px][oc]);
            }
        }
        __syncthreads();
    }

    // Epilogue: stage through smem (aliases buf, safe after final sync) for
    // coalesced stores; bias + ReLU.
    float* out_sh = buf;
    #pragma unroll
    for (int px=0; px<PXT; px++)
        #pragma unroll
        for (int oc=0; oc<OCT; oc++)
            out_sh[(og*OCT+oc)*TP + pg*PXT + px] = acc[px][oc];
    __syncthreads();
    for (int i=tid; i<OUTF; i+=256){
        int o = i/TP; int p = i & (TP-1);
        float v = out_sh[i] + bias[o];
        out[((size_t)b*COUT + o)*HWn + rem + p] = fmaxf(v, 0.f);
    }
}

// ---------------------------------------------------------------------------
extern "C" void kernel_launch(void* const* d_in, const int* in_sizes, int n_in,
                              void* d_out, int out_size)
{
    (void)in_sizes; (void)n_in; (void)out_size;
    const float* x       = (const float*)d_in[0];
    const float* w_off1  = (const float*)d_in[1];
    const float* b_off1  = (const float*)d_in[2];
    const float* w_mask1 = (const float*)d_in[3];
    const float* b_mask1 = (const float*)d_in[4];
    const float* w1      = (const float*)d_in[5];
    const float* b1      = (const float*)d_in[6];
    const float* w_off2  = (const float*)d_in[7];
    const float* b_off2  = (const float*)d_in[8];
    const float* w_mask2 = (const float*)d_in[9];
    const float* b_mask2 = (const float*)d_in[10];
    const float* w2      = (const float*)d_in[11];
    const float* b2      = (const float*)d_in[12];
    float* out = (float*)d_out;

    float *p_off1, *p_mask1, *p_h, *p_off2, *p_mask2;
    cudaGetSymbolAddress((void**)&p_off1,  g_off1);
    cudaGetSymbolAddress((void**)&p_mask1, g_mask1);
    cudaGetSymbolAddress((void**)&p_h,     g_h);
    cudaGetSymbolAddress((void**)&p_off2,  g_off2);
    cudaGetSymbolAddress((void**)&p_mask2, g_mask2);

    // Layer 1
    offmask_kernel<3,3><<<Bn*8*8, 256>>>(x, w_off1, b_off1, w_mask1, b_mask1,
                                         p_off1, p_mask1);
    deform_kernel<3,64,3,2><<<Bn*HWn/64, 256>>>(x, p_off1, p_mask1, w1, b1, p_h);
    // Layer 2
    offmask_kernel<64,8><<<Bn*8*8, 256>>>(p_h, w_off2, b_off2, w_mask2, b_mask2,
                                          p_off2, p_mask2);
    deform_kernel<64,128,4,4><<<Bn*HWn/64, 256>>>(p_h, p_off2, p_mask2, w2, b2, out);
}

// round 2
// speedup vs baseline: 1.0509x; 1.0509x over previous
#include <cuda_runtime.h>
#include <math.h>

// Problem constants
#define Bn  4
#define Hn  128
#define Wn  128
#define HWn (Hn*Wn)

// Intermediate scratch (device globals: no allocation allowed)
__device__ float g_off1[Bn*18*HWn];
__device__ float g_mask1[Bn*9*HWn];
__device__ float g_h   [Bn*64*HWn];
__device__ float g_off2[Bn*18*HWn];
__device__ float g_mask2[Bn*9*HWn];

// ---------------------------------------------------------------------------
// f32x2 helpers (FFMA2 — packed fp32 FMA, 2 MACs/lane; PTX-only path)
// ---------------------------------------------------------------------------
__device__ __forceinline__ unsigned long long f32x2_dup(float w){
    unsigned long long d;
    asm("mov.b64 %0, {%1, %1};" : "=l"(d) : "r"(__float_as_uint(w)));
    return d;
}
__device__ __forceinline__ void fma_f32x2(unsigned long long& acc,
                                          unsigned long long a,
                                          unsigned long long b){
    asm("fma.rn.f32x2 %0, %1, %2, %0;" : "+l"(acc) : "l"(a), "l"(b));
}

// ---------------------------------------------------------------------------
// offset/mask conv: y[0:18] = conv3x3(in, w_off)+b_off ; y[18:27] = sigmoid(conv+b_mask)
// Block = 16x16 pixel tile, 256 threads, channel-chunked (CC).
// ---------------------------------------------------------------------------
template<int CIN, int CC>
__global__ __launch_bounds__(256)
void offmask_kernel(const float* __restrict__ in,
                    const float* __restrict__ w_off, const float* __restrict__ b_off,
                    const float* __restrict__ w_mask, const float* __restrict__ b_mask,
                    float* __restrict__ off_out, float* __restrict__ mask_out)
{
    constexpr int NCH = CIN/CC;
    __shared__ float tile[CC][18][18];
    __shared__ float wsh[CC*9][28];   // [c*9+k][m], m padded 27->28

    int tid = threadIdx.x;
    int blk = blockIdx.x;
    int bx = blk & 7;          // Wn/16 == 8
    int by = (blk >> 3) & 7;   // Hn/16 == 8
    int b  = blk >> 6;
    int h0 = by*16, w0 = bx*16;
    int ty = tid >> 4, tx = tid & 15;

    float acc[28];
    #pragma unroll
    for (int i=0;i<28;i++) acc[i] = 0.f;

    for (int ch=0; ch<NCH; ch++){
        int c0 = ch*CC;
        for (int i=tid; i<CC*18*18; i+=256){
            int c = i/(18*18); int r = (i/18)%18; int col = i%18;
            int gy = h0-1+r, gx = w0-1+col;
            float v = 0.f;
            if (gy>=0 && gy<Hn && gx>=0 && gx<Wn)
                v = in[((b*CIN + c0+c)*Hn + gy)*Wn + gx];
            tile[c][r][col] = v;
        }
        for (int i=tid; i<CC*9; i+=256) wsh[i][27] = 0.f;
        for (int i=tid; i<CC*9*27; i+=256){
            int ck = i % (CC*9); int m = i / (CC*9);
            int c = ck/9, k = ck - c*9;
            wsh[ck][m] = (m < 18) ? w_off [(m*CIN + c0+c)*9 + k]
                                  : w_mask[((m-18)*CIN + c0+c)*9 + k];
        }
        __syncthreads();
        #pragma unroll
        for (int c=0;c<CC;c++){
            float nb[9];
            #pragma unroll
            for (int ky=0;ky<3;ky++)
                #pragma unroll
                for (int kx=0;kx<3;kx++)
                    nb[ky*3+kx] = tile[c][ty+ky][tx+kx];
            #pragma unroll
            for (int k=0;k<9;k++){
                float v = nb[k];
                const float4* w4 = (const float4*)(&wsh[c*9+k][0]);
                #pragma unroll
                for (int mg=0; mg<7; mg++){
                    float4 wv = w4[mg];
                    acc[mg*4+0] = fmaf(v, wv.x, acc[mg*4+0]);
                    acc[mg*4+1] = fmaf(v, wv.y, acc[mg*4+1]);
                    acc[mg*4+2] = fmaf(v, wv.z, acc[mg*4+2]);
                    acc[mg*4+3] = fmaf(v, wv.w, acc[mg*4+3]);
                }
            }
        }
        __syncthreads();
    }
    int hw = (h0+ty)*Wn + (w0+tx);
    #pragma unroll
    for (int m=0;m<18;m++)
        off_out[(b*18+m)*HWn + hw] = acc[m] + b_off[m];
    #pragma unroll
    for (int m=0;m<9;m++){
        float v = acc[18+m] + b_mask[m];
        mask_out[(b*9+m)*HWn + hw] = 1.f/(1.f + expf(-v));
    }
}

// ---------------------------------------------------------------------------
// Layer-1 deformable conv (CIN=3 tiny): original scheme (not the bottleneck).
// ---------------------------------------------------------------------------
template<int CIN, int COUT, int CC, int OCT>
__global__ __launch_bounds__(256)
void deform_kernel(const float* __restrict__ in,
                   const float* __restrict__ off, const float* __restrict__ mask,
                   const float* __restrict__ wgt, const float* __restrict__ bias,
                   float* __restrict__ out)
{
    constexpr int TP  = 64;
    constexpr int OG  = COUT/OCT;
    constexpr int NPG = 256/OG;
    constexpr int PXT = TP/NPG;
    constexpr int NCH = CIN/CC;
    constexpr int PARAMF = 5*9*TP;
    constexpr int WF = CC*9*COUT;
    constexpr int SF = 9*CC*TP;
    constexpr int MAINF = PARAMF + WF + SF;
    constexpr int OUTF  = COUT*TP;
    constexpr int SMEMF = (MAINF > OUTF) ? MAINF : OUTF;
    __shared__ __align__(16) float buf[SMEMF];

    int*   y0_sh  = (int*)buf;
    int*   x0_sh  = (int*)(buf + 9*TP);
    float* wy1_sh = buf + 2*9*TP;
    float* wx1_sh = buf + 3*9*TP;
    float* mm_sh  = buf + 4*9*TP;
    float* w_sh   = buf + PARAMF;
    float* samp_sh= buf + PARAMF + WF;

    int tid  = threadIdx.x;
    int base = blockIdx.x * TP;
    int b    = base / HWn;
    int rem  = base - b*HWn;
    int h    = rem / Wn;
    int w0   = rem - h*Wn;

    for (int s=tid; s<9*TP; s+=256){
        int p = s & (TP-1); int k = s/TP;
        int wpix = w0 + p;
        int hw = h*Wn + wpix;
        float dy = off[(b*18 + 2*k  )*HWn + hw];
        float dx = off[(b*18 + 2*k+1)*HWn + hw];
        float mm = mask[(b*9 + k)*HWn + hw];
        int ky = k/3, kx = k - ky*3;
        float py = dy + (float)(h - 1 + ky);
        float px = dx + (float)(wpix - 1 + kx);
        float fy = floorf(py), fx = floorf(px);
        y0_sh[s]  = (int)fy;
        x0_sh[s]  = (int)fx;
        wy1_sh[s] = py - fy;
        wx1_sh[s] = px - fx;
        mm_sh[s]  = mm;
    }

    float acc[PXT][OCT];
    #pragma unroll
    for (int i=0;i<PXT;i++)
        #pragma unroll
        for (int j=0;j<OCT;j++) acc[i][j] = 0.f;

    int og = tid % OG;
    int pg = tid / OG;

    __syncthreads();

    for (int ch=0; ch<NCH; ch++){
        int c0 = ch*CC;
        for (int i=tid; i<WF; i+=256){
            int o = i/(CC*9); int r = i - o*(CC*9); int c = r/9, k = r - c*9;
            w_sh[(c*9+k)*COUT + o] = wgt[(o*CIN + c0+c)*9 + k];
        }
        for (int s=tid; s<9*CC*TP; s+=256){
            int p = s & (TP-1); int cc = (s/TP)%CC; int k = s/(TP*CC);
            int kp = k*TP + p;
            int y0 = y0_sh[kp], x0 = x0_sh[kp];
            float wy1 = wy1_sh[kp], wx1 = wx1_sh[kp];
            float wy0 = 1.f-wy1, wx0 = 1.f-wx1;
            const float* cp = in + (size_t)(b*CIN + c0+cc)*HWn;
            int y1 = y0+1, x1 = x0+1;
            bool vy0 = (unsigned)y0 < (unsigned)Hn;
            bool vy1 = (unsigned)y1 < (unsigned)Hn;
            bool vx0 = (unsigned)x0 < (unsigned)Wn;
            bool vx1 = (unsigned)x1 < (unsigned)Wn;
            float v = 0.f;
            if (vy0 && vx0) v = fmaf(cp[y0*Wn+x0], wy0*wx0, v);
            if (vy0 && vx1) v = fmaf(cp[y0*Wn+x1], wy0*wx1, v);
            if (vy1 && vx0) v = fmaf(cp[y1*Wn+x0], wy1*wx0, v);
            if (vy1 && vx1) v = fmaf(cp[y1*Wn+x1], wy1*wx1, v);
            samp_sh[(k*CC+cc)*TP + p] = v * mm_sh[kp];
        }
        __syncthreads();
        #pragma unroll
        for (int c=0;c<CC;c++){
            #pragma unroll
            for (int k=0;k<9;k++){
                float wv[OCT];
                const float* wp = w_sh + (c*9+k)*COUT + og*OCT;
                if constexpr (OCT == 4){
                    float4 t = *(const float4*)wp;
                    wv[0]=t.x; wv[1]=t.y; wv[2]=t.z; wv[3]=t.w;
                } else {
                    float2 t = *(const float2*)wp;
                    wv[0]=t.x; wv[1]=t.y;
                }
                const float* sp = samp_sh + (k*CC+c)*TP + pg*PXT;
                float4 s0 = *(const float4*)sp;
                float4 s1 = *(const float4*)(sp+4);
                float sv[8] = {s0.x,s0.y,s0.z,s0.w,s1.x,s1.y,s1.z,s1.w};
                #pragma unroll
                for (int px=0; px<PXT; px++)
                    #pragma unroll
                    for (int oc=0; oc<OCT; oc++)
                        acc[px][oc] = fmaf(sv[px], wv[oc], acc[px][oc]);
            }
        }
        __syncthreads();
    }

    float* out_sh = buf;
    #pragma unroll
    for (int px=0; px<PXT; px++)
        #pragma unroll
        for (int oc=0; oc<OCT; oc++)
            out_sh[(og*OCT+oc)*TP + pg*PXT + px] = acc[px][oc];
    __syncthreads();
    for (int i=tid; i<OUTF; i+=256){
        int o = i/TP; int p = i & (TP-1);
        float v = out_sh[i] + bias[o];
        out[((size_t)b*COUT + o)*HWn + rem + p] = fmaxf(v, 0.f);
    }
}

// ---------------------------------------------------------------------------
// Layer-2 deformable conv, f32x2 + software-pipelined gather.
//   CIN=64, COUT=128, CC=4, TP=64 (TP*CC == 256 threads exactly).
//   Params (per k,pixel): 4 clamped corner flat-offsets + 4 validity/mask-
//   folded bilinear weights, computed ONCE.
//   Pipeline: prefetch chunk ch+1 gather LDGs into regs -> GEMM(ch) ->
//   barrier -> combine+STS(ch+1) -> barrier.
//   GEMM: acc pairs over adjacent pixels via fma.rn.f32x2 (2 MACs/lane).
// ---------------------------------------------------------------------------
template<int CIN, int COUT>
__global__ __launch_bounds__(256, 2)
void deform2_kernel(const float* __restrict__ in,
                    const float* __restrict__ off, const float* __restrict__ mask,
                    const float* __restrict__ wgt, const float* __restrict__ bias,
                    float* __restrict__ out)
{
    constexpr int TP  = 64;
    constexpr int CC  = 4;
    constexpr int NCH = CIN/CC;     // 16
    constexpr int OCT = 4;
    constexpr int OG  = COUT/OCT;   // 32 (lane id)
    constexpr int PXT = 8;          // pixels per thread (pg = warp id)
    constexpr int KP  = 9*TP;       // 576
    constexpr int WF  = CC*9*COUT;  // 4608
    constexpr int SF  = 9*CC*TP;    // 2304
    constexpr int ELEMS = 9;        // gather elems per thread per chunk (9*CC*TP/256)
    constexpr int SMEMF = 8*KP + WF + SF;     // 11520 floats = 46080 B
    __shared__ __align__(16) float smem[SMEMF];

    int*   off_sh = (int*)smem;               // [4][KP] corner flat offsets
    float* wgt_sh = smem + 4*KP;              // [4][KP] folded weights
    float* w_sh   = smem + 8*KP;              // [CC*9][COUT]
    float* samp_sh= smem + 8*KP + WF;         // [9][CC][TP]

    int tid  = threadIdx.x;
    int base = blockIdx.x * TP;
    int b    = base / HWn;
    int rem  = base - b*HWn;
    int h    = rem / Wn;
    int w0   = rem - h*Wn;

    // ---- Phase 0: per-(k,pixel) bilinear params (once) ----
    for (int s=tid; s<KP; s+=256){
        int p = s & 63, k = s >> 6;
        int wpix = w0 + p;
        int hw = h*Wn + wpix;
        float dy = off[(b*18 + 2*k  )*HWn + hw];
        float dx = off[(b*18 + 2*k+1)*HWn + hw];
        float mm = mask[(b*9 + k)*HWn + hw];
        int ky = k/3, kx = k - ky*3;
        float py = dy + (float)(h - 1 + ky);
        float px = dx + (float)(wpix - 1 + kx);
        float fy = floorf(py), fx = floorf(px);
        int y0 = (int)fy, x0 = (int)fx;
        int y1 = y0+1, x1 = x0+1;
        float wy1 = py - fy, wx1 = px - fx;
        float wy0 = 1.f - wy1, wx0 = 1.f - wx1;
        bool vy0 = (unsigned)y0 < (unsigned)Hn;
        bool vy1 = (unsigned)y1 < (unsigned)Hn;
        bool vx0 = (unsigned)x0 < (unsigned)Wn;
        bool vx1 = (unsigned)x1 < (unsigned)Wn;
        int y0c = min(max(y0,0),Hn-1), y1c = min(max(y1,0),Hn-1);
        int x0c = min(max(x0,0),Wn-1), x1c = min(max(x1,0),Wn-1);
        off_sh[0*KP+s] = y0c*Wn + x0c;  wgt_sh[0*KP+s] = (vy0&&vx0) ? wy0*wx0*mm : 0.f;
        off_sh[1*KP+s] = y0c*Wn + x1c;  wgt_sh[1*KP+s] = (vy0&&vx1) ? wy0*wx1*mm : 0.f;
        off_sh[2*KP+s] = y1c*Wn + x0c;  wgt_sh[2*KP+s] = (vy1&&vx0) ? wy1*wx0*mm : 0.f;
        off_sh[3*KP+s] = y1c*Wn + x1c;  wgt_sh[3*KP+s] = (vy1&&vx1) ? wy1*wx1*mm : 0.f;
    }
    __syncthreads();

    const float* in_b = in + (size_t)b*CIN*HWn;
    int og = tid & 31;        // lane  -> output-channel group
    int pg = tid >> 5;        // warp  -> pixel group

    unsigned long long acc[PXT/2][OCT];
    #pragma unroll
    for (int i=0;i<PXT/2;i++)
        #pragma unroll
        for (int j=0;j<OCT;j++) acc[i][j] = 0ULL;

    float pv[ELEMS][4];       // prefetched corner values for next chunk

    // prefetch + combine for a chunk
    auto prefetch = [&](int ch){
        int c0 = ch*CC;
        #pragma unroll
        for (int e=0;e<ELEMS;e++){
            int s = tid + e*256;          // s in [0, 9*CC*TP)
            int p = s & 63, c = (s>>6)&3, k = s>>8;
            int kp = (k<<6) + p;
            const float* cp = in_b + (size_t)(c0+c)*HWn;
            pv[e][0] = __ldg(cp + off_sh[0*KP+kp]);
            pv[e][1] = __ldg(cp + off_sh[1*KP+kp]);
            pv[e][2] = __ldg(cp + off_sh[2*KP+kp]);
            pv[e][3] = __ldg(cp + off_sh[3*KP+kp]);
        }
    };
    auto combine_store = [&](int ch){
        int c0 = ch*CC;
        // weights: straight global->smem (L2-resident, MLP across 18)
        #pragma unroll
        for (int j=0;j<18;j++){
            int i = tid + j*256;          // i in [0, WF)
            int o = i/(CC*9); int r = i - o*(CC*9); int c = r/9, kk = r - c*9;
            w_sh[(c*9+kk)*COUT + o] = __ldg(wgt + (o*CIN + c0+c)*9 + kk);
        }
        #pragma unroll
        for (int e=0;e<ELEMS;e++){
            int s = tid + e*256;
            int p = s & 63, c = (s>>6)&3, k = s>>8;
            int kp = (k<<6) + p;
            float v = pv[e][0]*wgt_sh[0*KP+kp]
                    + pv[e][1]*wgt_sh[1*KP+kp]
                    + pv[e][2]*wgt_sh[2*KP+kp]
                    + pv[e][3]*wgt_sh[3*KP+kp];
            samp_sh[(k*CC+c)*TP + p] = v;
        }
    };

    // prologue: fill chunk 0
    prefetch(0);
    combine_store(0);
    __syncthreads();

    for (int ch=0; ch<NCH; ch++){
        if (ch+1 < NCH) prefetch(ch+1);
        // ---- GEMM on current chunk (f32x2) ----
        #pragma unroll
        for (int c=0;c<CC;c++){
            #pragma unroll
            for (int k=0;k<9;k++){
                float4 wv = *(const float4*)(w_sh + (c*9+k)*COUT + og*OCT);
                unsigned long long wd[OCT];
                wd[0] = f32x2_dup(wv.x); wd[1] = f32x2_dup(wv.y);
                wd[2] = f32x2_dup(wv.z); wd[3] = f32x2_dup(wv.w);
                const ulonglong2* sp =
                    (const ulonglong2*)(samp_sh + (k*CC+c)*TP + pg*PXT);
                ulonglong2 sa = sp[0], sb = sp[1];
                unsigned long long sv2[4] = {sa.x, sa.y, sb.x, sb.y};
                #pragma unroll
                for (int pp=0; pp<PXT/2; pp++)
                    #pragma unroll
                    for (int oc=0; oc<OCT; oc++)
                        fma_f32x2(acc[pp][oc], sv2[pp], wd[oc]);
            }
        }
        __syncthreads();
        if (ch+1 < NCH){
            combine_store(ch+1);
            __syncthreads();
        }
    }

    // ---- Epilogue: stage via smem (aliases everything; all reads done) ----
    __syncthreads();
    float* out_sh = smem;     // COUT*TP = 8192 floats, fits in SMEMF
    #pragma unroll
    for (int pp=0; pp<PXT/2; pp++)
        #pragma unroll
        for (int oc=0; oc<OCT; oc++){
            uint2 u; 
            asm("mov.b64 {%0, %1}, %2;" : "=r"(u.x), "=r"(u.y) : "l"(acc[pp][oc]));
            out_sh[(og*OCT+oc)*TP + pg*PXT + pp*2 + 0] = __uint_as_float(u.x);
            out_sh[(og*OCT+oc)*TP + pg*PXT + pp*2 + 1] = __uint_as_float(u.y);
        }
    __syncthreads();
    for (int i=tid; i<COUT*TP; i+=256){
        int o = i>>6; int p = i & 63;
        float v = out_sh[i] + bias[o];
        out[((size_t)b*COUT + o)*HWn + rem + p] = fmaxf(v, 0.f);
    }
}

// ---------------------------------------------------------------------------
extern "C" void kernel_launch(void* const* d_in, const int* in_sizes, int n_in,
                              void* d_out, int out_size)
{
    (void)in_sizes; (void)n_in; (void)out_size;
    const float* x       = (const float*)d_in[0];
    const float* w_off1  = (const float*)d_in[1];
    const float* b_off1  = (const float*)d_in[2];
    const float* w_mask1 = (const float*)d_in[3];
    const float* b_mask1 = (const float*)d_in[4];
    const float* w1      = (const float*)d_in[5];
    const float* b1      = (const float*)d_in[6];
    const float* w_off2  = (const float*)d_in[7];
    const float* b_off2  = (const float*)d_in[8];
    const float* w_mask2 = (const float*)d_in[9];
    const float* b_mask2 = (const float*)d_in[10];
    const float* w2      = (const float*)d_in[11];
    const float* b2      = (const float*)d_in[12];
    float* out = (float*)d_out;

    float *p_off1, *p_mask1, *p_h, *p_off2, *p_mask2;
    cudaGetSymbolAddress((void**)&p_off1,  g_off1);
    cudaGetSymbolAddress((void**)&p_mask1, g_mask1);
    cudaGetSymbolAddress((void**)&p_h,     g_h);
    cudaGetSymbolAddress((void**)&p_off2,  g_off2);
    cudaGetSymbolAddress((void**)&p_mask2, g_mask2);

    // Layer 1
    offmask_kernel<3,3><<<Bn*8*8, 256>>>(x, w_off1, b_off1, w_mask1, b_mask1,
                                         p_off1, p_mask1);
    deform_kernel<3,64,3,2><<<Bn*HWn/64, 256>>>(x, p_off1, p_mask1, w1, b1, p_h);
    // Layer 2
    offmask_kernel<64,8><<<Bn*8*8, 256>>>(p_h, w_off2, b_off2, w_mask2, b_mask2,
                                          p_off2, p_mask2);
    deform2_kernel<64,128><<<Bn*HWn/64, 256>>>(p_h, p_off2, p_mask2, w2, b2, out);
}

// round 4
// speedup vs baseline: 1.7437x; 1.6593x over previous
#include <cuda_runtime.h>
#include <cstdint>
#include <math.h>

// Problem constants
#define Bn  4
#define Hn  128
#define Wn  128
#define HWn (Hn*Wn)

// Intermediate scratch (device globals: no allocation allowed)
__device__ float g_off1[Bn*18*HWn];
__device__ float g_mask1[Bn*9*HWn];
__device__ float g_h   [Bn*64*HWn];
__device__ float g_off2[Bn*18*HWn];
__device__ float g_mask2[Bn*9*HWn];
__device__ float g_w1t[3*9*64];     // w1 transposed: [c][k][o]
__device__ float g_w2t[64*9*128];   // w2 transposed: [c][k][o]

// ---------------------------------------------------------------------------
// f32x2 helpers (FFMA2 — packed fp32 FMA, 2 MACs/lane; PTX-only path)
// ---------------------------------------------------------------------------
__device__ __forceinline__ unsigned long long f32x2_dup(float w){
    unsigned long long d;
    asm("mov.b64 %0, {%1, %1};" : "=l"(d) : "r"(__float_as_uint(w)));
    return d;
}
__device__ __forceinline__ void fma_f32x2(unsigned long long& acc,
                                          unsigned long long a,
                                          unsigned long long b){
    asm("fma.rn.f32x2 %0, %1, %2, %0;" : "+l"(acc) : "l"(a), "l"(b));
}
__device__ __forceinline__ void cp_async16(unsigned int s, const void* g){
    asm volatile("cp.async.cg.shared.global [%0], [%1], 16;" :: "r"(s), "l"(g));
}
__device__ __forceinline__ void cp_commit(){
    asm volatile("cp.async.commit_group;");
}
__device__ __forceinline__ void cp_wait0(){
    asm volatile("cp.async.wait_group 0;");
}

// ---------------------------------------------------------------------------
// One-time weight transpose: w*t[(c*9+k)*COUT + o] = w[(o*CIN+c)*9 + k]
// ---------------------------------------------------------------------------
__global__ void wtrans_kernel(const float* __restrict__ w1, const float* __restrict__ w2,
                              float* __restrict__ w1t, float* __restrict__ w2t)
{
    int i = blockIdx.x*256 + threadIdx.x;
    if (i < 3*9*64){
        int o = i & 63; int ck = i >> 6; int c = ck/9, k = ck - 9*c;
        w1t[i] = w1[(o*3 + c)*9 + k];
    }
    if (i < 64*9*128){
        int o = i & 127; int ck = i >> 7; int c = ck/9, k = ck - 9*c;
        w2t[i] = w2[(o*64 + c)*9 + k];
    }
}

// ---------------------------------------------------------------------------
// offset/mask conv: y[0:18] = conv3x3(in, w_off)+b_off ; y[18:27] = sigmoid(conv+b_mask)
// ---------------------------------------------------------------------------
template<int CIN, int CC>
__global__ __launch_bounds__(256)
void offmask_kernel(const float* __restrict__ in,
                    const float* __restrict__ w_off, const float* __restrict__ b_off,
                    const float* __restrict__ w_mask, const float* __restrict__ b_mask,
                    float* __restrict__ off_out, float* __restrict__ mask_out)
{
    constexpr int NCH = CIN/CC;
    __shared__ float tile[CC][18][18];
    __shared__ float wsh[CC*9][28];

    int tid = threadIdx.x;
    int blk = blockIdx.x;
    int bx = blk & 7;
    int by = (blk >> 3) & 7;
    int b  = blk >> 6;
    int h0 = by*16, w0 = bx*16;
    int ty = tid >> 4, tx = tid & 15;

    float acc[28];
    #pragma unroll
    for (int i=0;i<28;i++) acc[i] = 0.f;

    for (int ch=0; ch<NCH; ch++){
        int c0 = ch*CC;
        for (int i=tid; i<CC*18*18; i+=256){
            int c = i/(18*18); int r = (i/18)%18; int col = i%18;
            int gy = h0-1+r, gx = w0-1+col;
            float v = 0.f;
            if (gy>=0 && gy<Hn && gx>=0 && gx<Wn)
                v = in[((b*CIN + c0+c)*Hn + gy)*Wn + gx];
            tile[c][r][col] = v;
        }
        for (int i=tid; i<CC*9; i+=256) wsh[i][27] = 0.f;
        for (int i=tid; i<CC*9*27; i+=256){
            int ck = i % (CC*9); int m = i / (CC*9);
            int c = ck/9, k = ck - c*9;
            wsh[ck][m] = (m < 18) ? w_off [(m*CIN + c0+c)*9 + k]
                                  : w_mask[((m-18)*CIN + c0+c)*9 + k];
        }
        __syncthreads();
        #pragma unroll
        for (int c=0;c<CC;c++){
            float nb[9];
            #pragma unroll
            for (int ky=0;ky<3;ky++)
                #pragma unroll
                for (int kx=0;kx<3;kx++)
                    nb[ky*3+kx] = tile[c][ty+ky][tx+kx];
            #pragma unroll
            for (int k=0;k<9;k++){
                float v = nb[k];
                const float4* w4 = (const float4*)(&wsh[c*9+k][0]);
                #pragma unroll
                for (int mg=0; mg<7; mg++){
                    float4 wv = w4[mg];
                    acc[mg*4+0] = fmaf(v, wv.x, acc[mg*4+0]);
                    acc[mg*4+1] = fmaf(v, wv.y, acc[mg*4+1]);
                    acc[mg*4+2] = fmaf(v, wv.z, acc[mg*4+2]);
                    acc[mg*4+3] = fmaf(v, wv.w, acc[mg*4+3]);
                }
            }
        }
        __syncthreads();
    }
    int hw = (h0+ty)*Wn + (w0+tx);
    #pragma unroll
    for (int m=0;m<18;m++)
        off_out[(b*18+m)*HWn + hw] = acc[m] + b_off[m];
    #pragma unroll
    for (int m=0;m<9;m++){
        float v = acc[18+m] + b_mask[m];
        mask_out[(b*9+m)*HWn + hw] = 1.f/(1.f + expf(-v));
    }
}

// ---------------------------------------------------------------------------
// Layer-1 deformable conv (CIN=3): staging uses pre-transposed weights.
// ---------------------------------------------------------------------------
template<int CIN, int COUT, int CC, int OCT>
__global__ __launch_bounds__(256)
void deform_kernel(const float* __restrict__ in,
                   const float* __restrict__ off, const float* __restrict__ mask,
                   const float* __restrict__ wt, const float* __restrict__ bias,
                   float* __restrict__ out)
{
    constexpr int TP  = 64;
    constexpr int OG  = COUT/OCT;
    constexpr int NPG = 256/OG;
    constexpr int PXT = TP/NPG;
    constexpr int NCH = CIN/CC;
    constexpr int PARAMF = 5*9*TP;
    constexpr int WF = CC*9*COUT;
    constexpr int SF = 9*CC*TP;
    constexpr int MAINF = PARAMF + WF + SF;
    constexpr int OUTF  = COUT*TP;
    constexpr int SMEMF = (MAINF > OUTF) ? MAINF : OUTF;
    __shared__ __align__(16) float buf[SMEMF];

    int*   y0_sh  = (int*)buf;
    int*   x0_sh  = (int*)(buf + 9*TP);
    float* wy1_sh = buf + 2*9*TP;
    float* wx1_sh = buf + 3*9*TP;
    float* mm_sh  = buf + 4*9*TP;
    float* w_sh   = buf + PARAMF;
    float* samp_sh= buf + PARAMF + WF;

    int tid  = threadIdx.x;
    int base = blockIdx.x * TP;
    int b    = base / HWn;
    int rem  = base - b*HWn;
    int h    = rem / Wn;
    int w0   = rem - h*Wn;

    for (int s=tid; s<9*TP; s+=256){
        int p = s & (TP-1); int k = s/TP;
        int wpix = w0 + p;
        int hw = h*Wn + wpix;
        float dy = off[(b*18 + 2*k  )*HWn + hw];
        float dx = off[(b*18 + 2*k+1)*HWn + hw];
        float mm = mask[(b*9 + k)*HWn + hw];
        int ky = k/3, kx = k - ky*3;
        float py = dy + (float)(h - 1 + ky);
        float px = dx + (float)(wpix - 1 + kx);
        float fy = floorf(py), fx = floorf(px);
        y0_sh[s]  = (int)fy;
        x0_sh[s]  = (int)fx;
        wy1_sh[s] = py - fy;
        wx1_sh[s] = px - fx;
        mm_sh[s]  = mm;
    }

    float acc[PXT][OCT];
    #pragma unroll
    for (int i=0;i<PXT;i++)
        #pragma unroll
        for (int j=0;j<OCT;j++) acc[i][j] = 0.f;

    int og = tid % OG;
    int pg = tid / OG;

    __syncthreads();

    for (int ch=0; ch<NCH; ch++){
        int c0 = ch*CC;
        // coalesced, conflict-free staging from pre-transposed weights
        for (int i=tid; i<WF; i+=256)
            w_sh[i] = wt[ch*WF + i];
        for (int s=tid; s<9*CC*TP; s+=256){
            int p = s & (TP-1); int cc = (s/TP)%CC; int k = s/(TP*CC);
            int kp = k*TP + p;
            int y0 = y0_sh[kp], x0 = x0_sh[kp];
            float wy1 = wy1_sh[kp], wx1 = wx1_sh[kp];
            float wy0 = 1.f-wy1, wx0 = 1.f-wx1;
            const float* cp = in + (size_t)(b*CIN + c0+cc)*HWn;
            int y1 = y0+1, x1 = x0+1;
            bool vy0 = (unsigned)y0 < (unsigned)Hn;
            bool vy1 = (unsigned)y1 < (unsigned)Hn;
            bool vx0 = (unsigned)x0 < (unsigned)Wn;
            bool vx1 = (unsigned)x1 < (unsigned)Wn;
            float v = 0.f;
            if (vy0 && vx0) v = fmaf(cp[y0*Wn+x0], wy0*wx0, v);
            if (vy0 && vx1) v = fmaf(cp[y0*Wn+x1], wy0*wx1, v);
            if (vy1 && vx0) v = fmaf(cp[y1*Wn+x0], wy1*wx0, v);
            if (vy1 && vx1) v = fmaf(cp[y1*Wn+x1], wy1*wx1, v);
            samp_sh[(k*CC+cc)*TP + p] = v * mm_sh[kp];
        }
        __syncthreads();
        #pragma unroll
        for (int c=0;c<CC;c++){
            #pragma unroll
            for (int k=0;k<9;k++){
                float wv[OCT];
                const float* wp = w_sh + (c*9+k)*COUT + og*OCT;
                if constexpr (OCT == 4){
                    float4 t = *(const float4*)wp;
                    wv[0]=t.x; wv[1]=t.y; wv[2]=t.z; wv[3]=t.w;
                } else {
                    float2 t = *(const float2*)wp;
                    wv[0]=t.x; wv[1]=t.y;
                }
                const float* sp = samp_sh + (k*CC+c)*TP + pg*PXT;
                float4 s0 = *(const float4*)sp;
                float4 s1 = *(const float4*)(sp+4);
                float sv[8] = {s0.x,s0.y,s0.z,s0.w,s1.x,s1.y,s1.z,s1.w};
                #pragma unroll
                for (int px=0; px<PXT; px++)
                    #pragma unroll
                    for (int oc=0; oc<OCT; oc++)
                        acc[px][oc] = fmaf(sv[px], wv[oc], acc[px][oc]);
            }
        }
        __syncthreads();
    }

    float* out_sh = buf;
    #pragma unroll
    for (int px=0; px<PXT; px++)
        #pragma unroll
        for (int oc=0; oc<OCT; oc++)
            out_sh[(og*OCT+oc)*TP + pg*PXT + px] = acc[px][oc];
    __syncthreads();
    for (int i=tid; i<OUTF; i+=256){
        int o = i/TP; int p = i & (TP-1);
        float v = out_sh[i] + bias[o];
        out[((size_t)b*COUT + o)*HWn + rem + p] = fmaxf(v, 0.f);
    }
}

// ---------------------------------------------------------------------------
// Layer-2 deformable conv v3:
//   - pre-transposed weights, staged via cp.async (conflict-free, overlapped)
//   - double-buffered weights + samples, ONE barrier per chunk
//   - f32x2 (FFMA2) GEMM, pixel-paired accumulators
// Dynamic smem: 73728 B -> 2 CTAs/SM.
// ---------------------------------------------------------------------------
template<int CIN, int COUT>
__global__ __launch_bounds__(256, 2)
void deform2_kernel(const float* __restrict__ in,
                    const float* __restrict__ off, const float* __restrict__ mask,
                    const float* __restrict__ wt, const float* __restrict__ bias,
                    float* __restrict__ out)
{
    constexpr int TP  = 64;
    constexpr int CC  = 4;
    constexpr int NCH = CIN/CC;     // 16
    constexpr int OCT = 4;
    constexpr int PXT = 8;
    constexpr int KP  = 9*TP;       // 576
    constexpr int WF  = CC*9*COUT;  // 4608
    constexpr int SF  = 9*CC*TP;    // 2304
    constexpr int ELEMS = 9;
    extern __shared__ __align__(16) float smem[];

    int*   off_sh = (int*)smem;               // [4][KP]
    float* wgt_sh = smem + 4*KP;              // [4][KP]
    float* w_shA  = smem + 8*KP;              // [WF] x2
    float* w_shB  = w_shA + WF;
    float* sampA  = w_shB + WF;               // [SF] x2
    float* sampB  = sampA + SF;

    int tid  = threadIdx.x;
    int base = blockIdx.x * TP;
    int b    = base / HWn;
    int rem  = base - b*HWn;
    int h    = rem / Wn;
    int w0   = rem - h*Wn;

    // ---- Phase 0: per-(k,pixel) bilinear params (once) ----
    for (int s=tid; s<KP; s+=256){
        int p = s & 63, k = s >> 6;
        int wpix = w0 + p;
        int hw = h*Wn + wpix;
        float dy = off[(b*18 + 2*k  )*HWn + hw];
        float dx = off[(b*18 + 2*k+1)*HWn + hw];
        float mm = mask[(b*9 + k)*HWn + hw];
        int ky = k/3, kx = k - ky*3;
        float py = dy + (float)(h - 1 + ky);
        float px = dx + (float)(wpix - 1 + kx);
        float fy = floorf(py), fx = floorf(px);
        int y0 = (int)fy, x0 = (int)fx;
        int y1 = y0+1, x1 = x0+1;
        float wy1 = py - fy, wx1 = px - fx;
        float wy0 = 1.f - wy1, wx0 = 1.f - wx1;
        bool vy0 = (unsigned)y0 < (unsigned)Hn;
        bool vy1 = (unsigned)y1 < (unsigned)Hn;
        bool vx0 = (unsigned)x0 < (unsigned)Wn;
        bool vx1 = (unsigned)x1 < (unsigned)Wn;
        int y0c = min(max(y0,0),Hn-1), y1c = min(max(y1,0),Hn-1);
        int x0c = min(max(x0,0),Wn-1), x1c = min(max(x1,0),Wn-1);
        off_sh[0*KP+s] = y0c*Wn + x0c;  wgt_sh[0*KP+s] = (vy0&&vx0) ? wy0*wx0*mm : 0.f;
        off_sh[1*KP+s] = y0c*Wn + x1c;  wgt_sh[1*KP+s] = (vy0&&vx1) ? wy0*wx1*mm : 0.f;
        off_sh[2*KP+s] = y1c*Wn + x0c;  wgt_sh[2*KP+s] = (vy1&&vx0) ? wy1*wx0*mm : 0.f;
        off_sh[3*KP+s] = y1c*Wn + x1c;  wgt_sh[3*KP+s] = (vy1&&vx1) ? wy1*wx1*mm : 0.f;
    }
    __syncthreads();

    const float* in_b = in + (size_t)b*CIN*HWn;
    int og = tid & 31;        // lane  -> output-channel group
    int pg = tid >> 5;        // warp  -> pixel group

    unsigned long long acc[PXT/2][OCT];
    #pragma unroll
    for (int i=0;i<PXT/2;i++)
        #pragma unroll
        for (int j=0;j<OCT;j++) acc[i][j] = 0ULL;

    float pv[ELEMS][4];

    auto stage_w = [&](int ch, float* dst){
        unsigned int d = (unsigned int)__cvta_generic_to_shared(dst);
        const float4* src = (const float4*)(wt + ch*WF);
        #pragma unroll
        for (int j=0;j<5;j++){
            int i = tid + j*256;
            if (i < WF/4) cp_async16(d + i*16, src + i);
        }
        cp_commit();
    };
    auto prefetch = [&](int ch){
        int c0 = ch*CC;
        #pragma unroll
        for (int e=0;e<ELEMS;e++){
            int s = tid + e*256;
            int p = s & 63, c = (s>>6)&3, k = s>>8;
            int kp = (k<<6) + p;
            const float* cp = in_b + (size_t)(c0+c)*HWn;
            pv[e][0] = __ldg(cp + off_sh[0*KP+kp]);
            pv[e][1] = __ldg(cp + off_sh[1*KP+kp]);
            pv[e][2] = __ldg(cp + off_sh[2*KP+kp]);
            pv[e][3] = __ldg(cp + off_sh[3*KP+kp]);
        }
    };
    auto combine_store = [&](float* dst){
        #pragma unroll
        for (int e=0;e<ELEMS;e++){
            int s = tid + e*256;
            int p = s & 63, c = (s>>6)&3, k = s>>8;
            int kp = (k<<6) + p;
            float v = pv[e][0]*wgt_sh[0*KP+kp]
                    + pv[e][1]*wgt_sh[1*KP+kp]
                    + pv[e][2]*wgt_sh[2*KP+kp]
                    + pv[e][3]*wgt_sh[3*KP+kp];
            dst[(k*CC+c)*TP + p] = v;
        }
    };
    auto gemm = [&](const float* wb, const float* sb){
        #pragma unroll
        for (int c=0;c<CC;c++){
            #pragma unroll
            for (int k=0;k<9;k++){
                float4 wv = *(const float4*)(wb + (c*9+k)*COUT + og*OCT);
                unsigned long long wd[OCT];
                wd[0] = f32x2_dup(wv.x); wd[1] = f32x2_dup(wv.y);
                wd[2] = f32x2_dup(wv.z); wd[3] = f32x2_dup(wv.w);
                const ulonglong2* sp = (const ulonglong2*)(sb + (k*CC+c)*TP + pg*PXT);
                ulonglong2 sa = sp[0], sb2 = sp[1];
                unsigned long long sv2[4] = {sa.x, sa.y, sb2.x, sb2.y};
                #pragma unroll
                for (int pp=0; pp<PXT/2; pp++)
                    #pragma unroll
                    for (int oc=0; oc<OCT; oc++)
                        fma_f32x2(acc[pp][oc], sv2[pp], wd[oc]);
            }
        }
    };

    // prologue: fill chunk 0
    stage_w(0, w_shA);
    prefetch(0);
    combine_store(sampA);
    cp_wait0();
    __syncthreads();

    for (int ch=0; ch<NCH; ch++){
        const float* wb = (ch & 1) ? w_shB : w_shA;
        const float* sb = (ch & 1) ? sampB : sampA;
        float* wn = (ch & 1) ? w_shA : w_shB;
        float* sn = (ch & 1) ? sampA : sampB;
        bool more = (ch+1 < NCH);
        if (more){
            stage_w(ch+1, wn);     // cp.async, background
            prefetch(ch+1);        // LDGs in flight under GEMM
        }
        gemm(wb, sb);
        if (more) combine_store(sn);
        cp_wait0();
        __syncthreads();           // single barrier per chunk
    }

    // ---- Epilogue: stage via smem (aliases; all reads done after barrier) ----
    float* out_sh = smem;          // COUT*TP = 8192 floats, fits
    #pragma unroll
    for (int pp=0; pp<PXT/2; pp++)
        #pragma unroll
        for (int oc=0; oc<OCT; oc++){
            uint2 u;
            asm("mov.b64 {%0, %1}, %2;" : "=r"(u.x), "=r"(u.y) : "l"(acc[pp][oc]));
            out_sh[(og*OCT+oc)*TP + pg*PXT + pp*2 + 0] = __uint_as_float(u.x);
            out_sh[(og*OCT+oc)*TP + pg*PXT + pp*2 + 1] = __uint_as_float(u.y);
        }
    __syncthreads();
    for (int i=tid; i<COUT*TP; i+=256){
        int o = i>>6; int p = i & 63;
        float v = out_sh[i] + bias[o];
        out[((size_t)b*COUT + o)*HWn + rem + p] = fmaxf(v, 0.f);
    }
}

// ---------------------------------------------------------------------------
extern "C" void kernel_launch(void* const* d_in, const int* in_sizes, int n_in,
                              void* d_out, int out_size)
{
    (void)in_sizes; (void)n_in; (void)out_size;
    const float* x       = (const float*)d_in[0];
    const float* w_off1  = (const float*)d_in[1];
    const float* b_off1  = (const float*)d_in[2];
    const float* w_mask1 = (const float*)d_in[3];
    const float* b_mask1 = (const float*)d_in[4];
    const float* w1      = (const float*)d_in[5];
    const float* b1      = (const float*)d_in[6];
    const float* w_off2  = (const float*)d_in[7];
    const float* b_off2  = (const float*)d_in[8];
    const float* w_mask2 = (const float*)d_in[9];
    const float* b_mask2 = (const float*)d_in[10];
    const float* w2      = (const float*)d_in[11];
    const float* b2      = (const float*)d_in[12];
    float* out = (float*)d_out;

    float *p_off1, *p_mask1, *p_h, *p_off2, *p_mask2, *p_w1t, *p_w2t;
    cudaGetSymbolAddress((void**)&p_off1,  g_off1);
    cudaGetSymbolAddress((void**)&p_mask1, g_mask1);
    cudaGetSymbolAddress((void**)&p_h,     g_h);
    cudaGetSymbolAddress((void**)&p_off2,  g_off2);
    cudaGetSymbolAddress((void**)&p_mask2, g_mask2);
    cudaGetSymbolAddress((void**)&p_w1t,   g_w1t);
    cudaGetSymbolAddress((void**)&p_w2t,   g_w2t);

    constexpr int D2_SMEM = (8*576 + 2*4608 + 2*2304) * 4;  // 73728 B
    cudaFuncSetAttribute(deform2_kernel<64,128>,
                         cudaFuncAttributeMaxDynamicSharedMemorySize, D2_SMEM);

    // Weight transposes (tiny, once per invocation)
    wtrans_kernel<<<288, 256>>>(w1, w2, p_w1t, p_w2t);
    // Layer 1
    offmask_kernel<3,3><<<Bn*8*8, 256>>>(x, w_off1, b_off1, w_mask1, b_mask1,
                                         p_off1, p_mask1);
    deform_kernel<3,64,3,2><<<Bn*HWn/64, 256>>>(x, p_off1, p_mask1, p_w1t, b1, p_h);
    // Layer 2
    offmask_kernel<64,8><<<Bn*8*8, 256>>>(p_h, w_off2, b_off2, w_mask2, b_mask2,
                                          p_off2, p_mask2);
    deform2_kernel<64,128><<<Bn*HWn/64, 256, D2_SMEM>>>(p_h, p_off2, p_mask2,
                                                        p_w2t, b2, out);
}

// round 6
// speedup vs baseline: 1.7444x; 1.0004x over previous
#include <cuda_runtime.h>
#include <cstdint>
#include <math.h>

// Problem constants
#define Bn  4
#define Hn  128
#define Wn  128
#define HWn (Hn*Wn)

// Intermediate scratch (device globals: no allocation allowed)
__device__ float g_off1[Bn*18*HWn];
__device__ float g_mask1[Bn*9*HWn];
__device__ float g_h   [Bn*64*HWn];
__device__ float g_off2[Bn*18*HWn];
__device__ float g_mask2[Bn*9*HWn];
__device__ float g_w1t[3*9*64];     // w1 transposed: [c][k][o]
__device__ float g_w2t[64*9*128];   // w2 transposed: [c][k][o]

// ---------------------------------------------------------------------------
// f32x2 helpers (FFMA2 — packed fp32 FMA, 2 MACs/lane; PTX-only path)
// ---------------------------------------------------------------------------
__device__ __forceinline__ unsigned long long f32x2_dup(float w){
    unsigned long long d;
    asm("mov.b64 %0, {%1, %1};" : "=l"(d) : "r"(__float_as_uint(w)));
    return d;
}
__device__ __forceinline__ void f32x2_unpack(unsigned long long v, float& lo, float& hi){
    unsigned int a, b;
    asm("mov.b64 {%0, %1}, %2;" : "=r"(a), "=r"(b) : "l"(v));
    lo = __uint_as_float(a); hi = __uint_as_float(b);
}
__device__ __forceinline__ void fma_f32x2(unsigned long long& acc,
                                          unsigned long long a,
                                          unsigned long long b){
    asm("fma.rn.f32x2 %0, %1, %2, %0;" : "+l"(acc) : "l"(a), "l"(b));
}
__device__ __forceinline__ void cp_async16(unsigned int s, const void* g){
    asm volatile("cp.async.cg.shared.global [%0], [%1], 16;" :: "r"(s), "l"(g));
}
__device__ __forceinline__ void cp_commit(){
    asm volatile("cp.async.commit_group;");
}
__device__ __forceinline__ void cp_wait0(){
    asm volatile("cp.async.wait_group 0;");
}

// ---------------------------------------------------------------------------
// One-time weight transpose: w*t[(c*9+k)*COUT + o] = w[(o*CIN+c)*9 + k]
// ---------------------------------------------------------------------------
__global__ void wtrans_kernel(const float* __restrict__ w1, const float* __restrict__ w2,
                              float* __restrict__ w1t, float* __restrict__ w2t)
{
    int i = blockIdx.x*256 + threadIdx.x;
    if (i < 3*9*64){
        int o = i & 63; int ck = i >> 6; int c = ck/9, k = ck - 9*c;
        w1t[i] = w1[(o*3 + c)*9 + k];
    }
    if (i < 64*9*128){
        int o = i & 127; int ck = i >> 7; int c = ck/9, k = ck - 9*c;
        w2t[i] = w2[(o*64 + c)*9 + k];
    }
}

// ---------------------------------------------------------------------------
// offset/mask conv v2: 2 adjacent pixels per thread, f32x2 paired over the
// 28 (padded) outputs. Weights m-fastest in smem -> ulonglong2 loads feed
// FFMA2 directly; samples dup'd via mov.b64 (ALU pipe).
// Block = 128 threads = 16x16 pixel tile (2 px/thread). Grid = Bn*64.
// ---------------------------------------------------------------------------
template<int CIN, int CC>
__global__ __launch_bounds__(128)
void offmask_kernel(const float* __restrict__ in,
                    const float* __restrict__ w_off, const float* __restrict__ b_off,
                    const float* __restrict__ w_mask, const float* __restrict__ b_mask,
                    float* __restrict__ off_out, float* __restrict__ mask_out)
{
    constexpr int NCH = CIN/CC;
    __shared__ float tile[CC][18][18];
    __shared__ __align__(16) float wsh[CC*9][28];   // row = 112B (16B aligned)

    int tid = threadIdx.x;
    int blk = blockIdx.x;
    int bx = blk & 7;
    int by = (blk >> 3) & 7;
    int b  = blk >> 6;
    int h0 = by*16, w0 = bx*16;
    int ty  = tid >> 3;        // 0..15
    int txp = tid & 7;         // 0..7  -> pixels 2txp, 2txp+1

    unsigned long long acc2[2][14];   // [pixel][m-pair]
    #pragma unroll
    for (int p=0;p<2;p++)
        #pragma unroll
        for (int j=0;j<14;j++) acc2[p][j] = 0ULL;

    for (int ch=0; ch<NCH; ch++){
        int c0 = ch*CC;
        for (int i=tid; i<CC*18*18; i+=128){
            int c = i/(18*18); int r = (i/18)%18; int col = i%18;
            int gy = h0-1+r, gx = w0-1+col;
            float v = 0.f;
            if (gy>=0 && gy<Hn && gx>=0 && gx<Wn)
                v = in[((b*CIN + c0+c)*Hn + gy)*Wn + gx];
            tile[c][r][col] = v;
        }
        for (int i=tid; i<CC*9; i+=128) wsh[i][27] = 0.f;
        for (int i=tid; i<CC*9*27; i+=128){
            int ck = i % (CC*9); int m = i / (CC*9);
            int c = ck/9, k = ck - c*9;
            wsh[ck][m] = (m < 18) ? w_off [(m*CIN + c0+c)*9 + k]
                                  : w_mask[((m-18)*CIN + c0+c)*9 + k];
        }
        __syncthreads();
        #pragma unroll
        for (int c=0;c<CC;c++){
            // register window: rows ty..ty+2, cols 2txp..2txp+3
            float2 wnd[3][2];
            #pragma unroll
            for (int r=0;r<3;r++){
                wnd[r][0] = *(const float2*)&tile[c][ty+r][2*txp];
                wnd[r][1] = *(const float2*)&tile[c][ty+r][2*txp+2];
            }
            #pragma unroll
            for (int ky=0;ky<3;ky++){
                #pragma unroll
                for (int kx=0;kx<3;kx++){
                    float s0 = (kx==0) ? wnd[ky][0].x : (kx==1) ? wnd[ky][0].y : wnd[ky][1].x;
                    float s1 = (kx==0) ? wnd[ky][0].y : (kx==1) ? wnd[ky][1].x : wnd[ky][1].y;
                    unsigned long long d0 = f32x2_dup(s0);
                    unsigned long long d1 = f32x2_dup(s1);
                    const ulonglong2* wp = (const ulonglong2*)&wsh[c*9 + ky*3 + kx][0];
                    #pragma unroll
                    for (int j=0;j<7;j++){
                        ulonglong2 wv = wp[j];
                        fma_f32x2(acc2[0][2*j  ], d0, wv.x);
                        fma_f32x2(acc2[0][2*j+1], d0, wv.y);
                        fma_f32x2(acc2[1][2*j  ], d1, wv.x);
                        fma_f32x2(acc2[1][2*j+1], d1, wv.y);
                    }
                }
            }
        }
        __syncthreads();
    }

    // Epilogue: float2 stores over the adjacent pixel pair.
    int hw = (h0+ty)*Wn + w0 + 2*txp;
    #pragma unroll
    for (int j=0;j<14;j++){
        float a0lo,a0hi,a1lo,a1hi;
        f32x2_unpack(acc2[0][j], a0lo, a0hi);
        f32x2_unpack(acc2[1][j], a1lo, a1hi);
        int m0 = 2*j, m1 = 2*j+1;
        if (m0 < 18){
            float bb = b_off[m0];
            float2 v = make_float2(a0lo+bb, a1lo+bb);
            *(float2*)&off_out[(b*18+m0)*HWn + hw] = v;
        } else {
            float bb = b_mask[m0-18];
            float2 v = make_float2(1.f/(1.f+expf(-(a0lo+bb))),
                                   1.f/(1.f+expf(-(a1lo+bb))));
            *(float2*)&mask_out[(b*9+m0-18)*HWn + hw] = v;
        }
        if (m1 < 18){
            float bb = b_off[m1];
            float2 v = make_float2(a0hi+bb, a1hi+bb);
            *(float2*)&off_out[(b*18+m1)*HWn + hw] = v;
        } else if (m1 < 27){
            float bb = b_mask[m1-18];
            float2 v = make_float2(1.f/(1.f+expf(-(a0hi+bb))),
                                   1.f/(1.f+expf(-(a1hi+bb))));
            *(float2*)&mask_out[(b*9+m1-18)*HWn + hw] = v;
        }
    }
}

// ---------------------------------------------------------------------------
// Layer-1 deformable conv (CIN=3): staging uses pre-transposed weights.
// ---------------------------------------------------------------------------
template<int CIN, int COUT, int CC, int OCT>
__global__ __launch_bounds__(256)
void deform_kernel(const float* __restrict__ in,
                   const float* __restrict__ off, const float* __restrict__ mask,
                   const float* __restrict__ wt, const float* __restrict__ bias,
                   float* __restrict__ out)
{
    constexpr int TP  = 64;
    constexpr int OG  = COUT/OCT;
    constexpr int NPG = 256/OG;
    constexpr int PXT = TP/NPG;
    constexpr int NCH = CIN/CC;
    constexpr int PARAMF = 5*9*TP;
    constexpr int WF = CC*9*COUT;
    constexpr int SF = 9*CC*TP;
    constexpr int MAINF = PARAMF + WF + SF;
    constexpr int OUTF  = COUT*TP;
    constexpr int SMEMF = (MAINF > OUTF) ? MAINF : OUTF;
    __shared__ __align__(16) float buf[SMEMF];

    int*   y0_sh  = (int*)buf;
    int*   x0_sh  = (int*)(buf + 9*TP);
    float* wy1_sh = buf + 2*9*TP;
    float* wx1_sh = buf + 3*9*TP;
    float* mm_sh  = buf + 4*9*TP;
    float* w_sh   = buf + PARAMF;
    float* samp_sh= buf + PARAMF + WF;

    int tid  = threadIdx.x;
    int base = blockIdx.x * TP;
    int b    = base / HWn;
    int rem  = base - b*HWn;
    int h    = rem / Wn;
    int w0   = rem - h*Wn;

    for (int s=tid; s<9*TP; s+=256){
        int p = s & (TP-1); int k = s/TP;
        int wpix = w0 + p;
        int hw = h*Wn + wpix;
        float dy = off[(b*18 + 2*k  )*HWn + hw];
        float dx = off[(b*18 + 2*k+1)*HWn + hw];
        float mm = mask[(b*9 + k)*HWn + hw];
        int ky = k/3, kx = k - ky*3;
        float py = dy + (float)(h - 1 + ky);
        float px = dx + (float)(wpix - 1 + kx);
        float fy = floorf(py), fx = floorf(px);
        y0_sh[s]  = (int)fy;
        x0_sh[s]  = (int)fx;
        wy1_sh[s] = py - fy;
        wx1_sh[s] = px - fx;
        mm_sh[s]  = mm;
    }

    float acc[PXT][OCT];
    #pragma unroll
    for (int i=0;i<PXT;i++)
        #pragma unroll
        for (int j=0;j<OCT;j++) acc[i][j] = 0.f;

    int og = tid % OG;
    int pg = tid / OG;

    __syncthreads();

    for (int ch=0; ch<NCH; ch++){
        int c0 = ch*CC;
        for (int i=tid; i<WF; i+=256)
            w_sh[i] = wt[ch*WF + i];
        for (int s=tid; s<9*CC*TP; s+=256){
            int p = s & (TP-1); int cc = (s/TP)%CC; int k = s/(TP*CC);
            int kp = k*TP + p;
            int y0 = y0_sh[kp], x0 = x0_sh[kp];
            float wy1 = wy1_sh[kp], wx1 = wx1_sh[kp];
            float wy0 = 1.f-wy1, wx0 = 1.f-wx1;
            const float* cp = in + (size_t)(b*CIN + c0+cc)*HWn;
            int y1 = y0+1, x1 = x0+1;
            bool vy0 = (unsigned)y0 < (unsigned)Hn;
            bool vy1 = (unsigned)y1 < (unsigned)Hn;
            bool vx0 = (unsigned)x0 < (unsigned)Wn;
            bool vx1 = (unsigned)x1 < (unsigned)Wn;
            float v = 0.f;
            if (vy0 && vx0) v = fmaf(cp[y0*Wn+x0], wy0*wx0, v);
            if (vy0 && vx1) v = fmaf(cp[y0*Wn+x1], wy0*wx1, v);
            if (vy1 && vx0) v = fmaf(cp[y1*Wn+x0], wy1*wx0, v);
            if (vy1 && vx1) v = fmaf(cp[y1*Wn+x1], wy1*wx1, v);
            samp_sh[(k*CC+cc)*TP + p] = v * mm_sh[kp];
        }
        __syncthreads();
        #pragma unroll
        for (int c=0;c<CC;c++){
            #pragma unroll
            for (int k=0;k<9;k++){
                float wv[OCT];
                const float* wp = w_sh + (c*9+k)*COUT + og*OCT;
                if constexpr (OCT == 4){
                    float4 t = *(const float4*)wp;
                    wv[0]=t.x; wv[1]=t.y; wv[2]=t.z; wv[3]=t.w;
                } else {
                    float2 t = *(const float2*)wp;
                    wv[0]=t.x; wv[1]=t.y;
                }
                const float* sp = samp_sh + (k*CC+c)*TP + pg*PXT;
                float4 s0 = *(const float4*)sp;
                float4 s1 = *(const float4*)(sp+4);
                float sv[8] = {s0.x,s0.y,s0.z,s0.w,s1.x,s1.y,s1.z,s1.w};
                #pragma unroll
                for (int px=0; px<PXT; px++)
                    #pragma unroll
                    for (int oc=0; oc<OCT; oc++)
                        acc[px][oc] = fmaf(sv[px], wv[oc], acc[px][oc]);
            }
        }
        __syncthreads();
    }

    float* out_sh = buf;
    #pragma unroll
    for (int px=0; px<PXT; px++)
        #pragma unroll
        for (int oc=0; oc<OCT; oc++)
            out_sh[(og*OCT+oc)*TP + pg*PXT + px] = acc[px][oc];
    __syncthreads();
    for (int i=tid; i<OUTF; i+=256){
        int o = i/TP; int p = i & (TP-1);
        float v = out_sh[i] + bias[o];
        out[((size_t)b*COUT + o)*HWn + rem + p] = fmaxf(v, 0.f);
    }
}

// ---------------------------------------------------------------------------
// Layer-2 deformable conv v3:
//   pre-transposed weights via cp.async, double-buffered, one barrier/chunk,
//   f32x2 GEMM with pixel-paired accumulators.
// ---------------------------------------------------------------------------
template<int CIN, int COUT>
__global__ __launch_bounds__(256, 2)
void deform2_kernel(const float* __restrict__ in,
                    const float* __restrict__ off, const float* __restrict__ mask,
                    const float* __restrict__ wt, const float* __restrict__ bias,
                    float* __restrict__ out)
{
    constexpr int TP  = 64;
    constexpr int CC  = 4;
    constexpr int NCH = CIN/CC;     // 16
    constexpr int OCT = 4;
    constexpr int PXT = 8;
    constexpr int KP  = 9*TP;       // 576
    constexpr int WF  = CC*9*COUT;  // 4608
    constexpr int SF  = 9*CC*TP;    // 2304
    constexpr int ELEMS = 9;
    extern __shared__ __align__(16) float smem[];

    int*   off_sh = (int*)smem;               // [4][KP]
    float* wgt_sh = smem + 4*KP;              // [4][KP]
    float* w_shA  = smem + 8*KP;              // [WF] x2
    float* w_shB  = w_shA + WF;
    float* sampA  = w_shB + WF;               // [SF] x2
    float* sampB  = sampA + SF;

    int tid  = threadIdx.x;
    int base = blockIdx.x * TP;
    int b    = base / HWn;
    int rem  = base - b*HWn;
    int h    = rem / Wn;
    int w0   = rem - h*Wn;

    for (int s=tid; s<KP; s+=256){
        int p = s & 63, k = s >> 6;
        int wpix = w0 + p;
        int hw = h*Wn + wpix;
        float dy = off[(b*18 + 2*k  )*HWn + hw];
        float dx = off[(b*18 + 2*k+1)*HWn + hw];
        float mm = mask[(b*9 + k)*HWn + hw];
        int ky = k/3, kx = k - ky*3;
        float py = dy + (float)(h - 1 + ky);
        float px = dx + (float)(wpix - 1 + kx);
        float fy = floorf(py), fx = floorf(px);
        int y0 = (int)fy, x0 = (int)fx;
        int y1 = y0+1, x1 = x0+1;
        float wy1 = py - fy, wx1 = px - fx;
        float wy0 = 1.f - wy1, wx0 = 1.f - wx1;
        bool vy0 = (unsigned)y0 < (unsigned)Hn;
        bool vy1 = (unsigned)y1 < (unsigned)Hn;
        bool vx0 = (unsigned)x0 < (unsigned)Wn;
        bool vx1 = (unsigned)x1 < (unsigned)Wn;
        int y0c = min(max(y0,0),Hn-1), y1c = min(max(y1,0),Hn-1);
        int x0c = min(max(x0,0),Wn-1), x1c = min(max(x1,0),Wn-1);
        off_sh[0*KP+s] = y0c*Wn + x0c;  wgt_sh[0*KP+s] = (vy0&&vx0) ? wy0*wx0*mm : 0.f;
        off_sh[1*KP+s] = y0c*Wn + x1c;  wgt_sh[1*KP+s] = (vy0&&vx1) ? wy0*wx1*mm : 0.f;
        off_sh[2*KP+s] = y1c*Wn + x0c;  wgt_sh[2*KP+s] = (vy1&&vx0) ? wy1*wx0*mm : 0.f;
        off_sh[3*KP+s] = y1c*Wn + x1c;  wgt_sh[3*KP+s] = (vy1&&vx1) ? wy1*wx1*mm : 0.f;
    }
    __syncthreads();

    const float* in_b = in + (size_t)b*CIN*HWn;
    int og = tid & 31;
    int pg = tid >> 5;

    unsigned long long acc[PXT/2][OCT];
    #pragma unroll
    for (int i=0;i<PXT/2;i++)
        #pragma unroll
        for (int j=0;j<OCT;j++) acc[i][j] = 0ULL;

    float pv[ELEMS][4];

    auto stage_w = [&](int ch, float* dst){
        unsigned int d = (unsigned int)__cvta_generic_to_shared(dst);
        const float4* src = (const float4*)(wt + ch*WF);
        #pragma unroll
        for (int j=0;j<5;j++){
            int i = tid + j*256;
            if (i < WF/4) cp_async16(d + i*16, src + i);
        }
        cp_commit();
    };
    auto prefetch = [&](int ch){
        int c0 = ch*CC;
        #pragma unroll
        for (int e=0;e<ELEMS;e++){
            int s = tid + e*256;
            int p = s & 63, c = (s>>6)&3, k = s>>8;
            int kp = (k<<6) + p;
            const float* cp = in_b + (size_t)(c0+c)*HWn;
            pv[e][0] = __ldg(cp + off_sh[0*KP+kp]);
            pv[e][1] = __ldg(cp + off_sh[1*KP+kp]);
            pv[e][2] = __ldg(cp + off_sh[2*KP+kp]);
            pv[e][3] = __ldg(cp + off_sh[3*KP+kp]);
        }
    };
    auto combine_store = [&](float* dst){
        #pragma unroll
        for (int e=0;e<ELEMS;e++){
            int s = tid + e*256;
            int p = s & 63, c = (s>>6)&3, k = s>>8;
            int kp = (k<<6) + p;
            float v = pv[e][0]*wgt_sh[0*KP+kp]
                    + pv[e][1]*wgt_sh[1*KP+kp]
                    + pv[e][2]*wgt_sh[2*KP+kp]
                    + pv[e][3]*wgt_sh[3*KP+kp];
            dst[(k*CC+c)*TP + p] = v;
        }
    };
    auto gemm = [&](const float* wb, const float* sb){
        #pragma unroll
        for (int c=0;c<CC;c++){
            #pragma unroll
            for (int k=0;k<9;k++){
                float4 wv = *(const float4*)(wb + (c*9+k)*COUT + og*OCT);
                unsigned long long wd[OCT];
                wd[0] = f32x2_dup(wv.x); wd[1] = f32x2_dup(wv.y);
                wd[2] = f32x2_dup(wv.z); wd[3] = f32x2_dup(wv.w);
                const ulonglong2* sp = (const ulonglong2*)(sb + (k*CC+c)*TP + pg*PXT);
                ulonglong2 sa = sp[0], sb2 = sp[1];
                unsigned long long sv2[4] = {sa.x, sa.y, sb2.x, sb2.y};
                #pragma unroll
                for (int pp=0; pp<PXT/2; pp++)
                    #pragma unroll
                    for (int oc=0; oc<OCT; oc++)
                        fma_f32x2(acc[pp][oc], sv2[pp], wd[oc]);
            }
        }
    };

    stage_w(0, w_shA);
    prefetch(0);
    combine_store(sampA);
    cp_wait0();
    __syncthreads();

    for (int ch=0; ch<NCH; ch++){
        const float* wb = (ch & 1) ? w_shB : w_shA;
        const float* sb = (ch & 1) ? sampB : sampA;
        float* wn = (ch & 1) ? w_shA : w_shB;
        float* sn = (ch & 1) ? sampA : sampB;
        bool more = (ch+1 < NCH);
        if (more){
            stage_w(ch+1, wn);
            prefetch(ch+1);
        }
        gemm(wb, sb);
        if (more) combine_store(sn);
        cp_wait0();
        __syncthreads();
    }

    float* out_sh = smem;
    #pragma unroll
    for (int pp=0; pp<PXT/2; pp++)
        #pragma unroll
        for (int oc=0; oc<OCT; oc++){
            float lo, hi;
            f32x2_unpack(acc[pp][oc], lo, hi);
            out_sh[(og*OCT+oc)*TP + pg*PXT + pp*2 + 0] = lo;
            out_sh[(og*OCT+oc)*TP + pg*PXT + pp*2 + 1] = hi;
        }
    __syncthreads();
    for (int i=tid; i<COUT*TP; i+=256){
        int o = i>>6; int p = i & 63;
        float v = out_sh[i] + bias[o];
        out[((size_t)b*COUT + o)*HWn + rem + p] = fmaxf(v, 0.f);
    }
}

// ---------------------------------------------------------------------------
extern "C" void kernel_launch(void* const* d_in, const int* in_sizes, int n_in,
                              void* d_out, int out_size)
{
    (void)in_sizes; (void)n_in; (void)out_size;
    const float* x       = (const float*)d_in[0];
    const float* w_off1  = (const float*)d_in[1];
    const float* b_off1  = (const float*)d_in[2];
    const float* w_mask1 = (const float*)d_in[3];
    const float* b_mask1 = (const float*)d_in[4];
    const float* w1      = (const float*)d_in[5];
    const float* b1      = (const float*)d_in[6];
    const float* w_off2  = (const float*)d_in[7];
    const float* b_off2  = (const float*)d_in[8];
    const float* w_mask2 = (const float*)d_in[9];
    const float* b_mask2 = (const float*)d_in[10];
    const float* w2      = (const float*)d_in[11];
    const float* b2      = (const float*)d_in[12];
    float* out = (float*)d_out;

    float *p_off1, *p_mask1, *p_h, *p_off2, *p_mask2, *p_w1t, *p_w2t;
    cudaGetSymbolAddress((void**)&p_off1,  g_off1);
    cudaGetSymbolAddress((void**)&p_mask1, g_mask1);
    cudaGetSymbolAddress((void**)&p_h,     g_h);
    cudaGetSymbolAddress((void**)&p_off2,  g_off2);
    cudaGetSymbolAddress((void**)&p_mask2, g_mask2);
    cudaGetSymbolAddress((void**)&p_w1t,   g_w1t);
    cudaGetSymbolAddress((void**)&p_w2t,   g_w2t);

    constexpr int D2_SMEM = (8*576 + 2*4608 + 2*2304) * 4;  // 73728 B
    cudaFuncSetAttribute(deform2_kernel<64,128>,
                         cudaFuncAttributeMaxDynamicSharedMemorySize, D2_SMEM);

    wtrans_kernel<<<288, 256>>>(w1, w2, p_w1t, p_w2t);
    // Layer 1
    offmask_kernel<3,3><<<Bn*8*8, 128>>>(x, w_off1, b_off1, w_mask1, b_mask1,
                                         p_off1, p_mask1);
    deform_kernel<3,64,3,2><<<Bn*HWn/64, 256>>>(x, p_off1, p_mask1, p_w1t, b1, p_h);
    // Layer 2
    offmask_kernel<64,8><<<Bn*8*8, 128>>>(p_h, w_off2, b_off2, w_mask2, b_mask2,
                                          p_off2, p_mask2);
    deform2_kernel<64,128><<<Bn*HWn/64, 256, D2_SMEM>>>(p_h, p_off2, p_mask2,
                                                        p_w2t, b2, out);
}